// round 3
// baseline (speedup 1.0000x reference)
#include <cuda_runtime.h>
#include <cuda_fp16.h>
#include <cstdint>
#include <cstddef>

#define NNODES 8192
#define INF_ 256
#define OUTF 64
#define ALPHA 0.2f
#define LOG2E 1.4426950408889634f
#define PSCALE 256.0f   // scales numerator & denominator identically (cancels)

// ---------------- device scratch (no allocations allowed) ----------------
__device__ __align__(16) __half g_hpH[(size_t)NNODES * 72]; // cols 0-63 h', col 64 = 1, 65-71 = 0
__device__ float g_s1[NNODES];
__device__ float g_B[NNODES];   // exp(s2_j)
__device__ float g_D[NNODES];   // exp(ALPHA*s2_j)
__device__ unsigned g_s2max_u;  // order-encoded float max of s2

__global__ void reset_kernel() { g_s2max_u = 0u; }

// ---------------- prep: h' = X@W (fp32), s1, s2, B, D, S2max ----------------
__global__ __launch_bounds__(512) void prep_kernel(const float* __restrict__ X,
                                                   const float* __restrict__ W,
                                                   const float* __restrict__ a1,
                                                   const float* __restrict__ a2) {
    __shared__ float sX[32][64];
    __shared__ float sW[64][64];
    int t = threadIdx.x;
    int r = t >> 4;           // 0..31 local row
    int q = t & 15;           // 0..15 -> 4 output cols each
    int k0 = q * 4;
    int R0 = blockIdx.x * 32;

    float4 acc = make_float4(0.f, 0.f, 0.f, 0.f);
    for (int c0 = 0; c0 < INF_; c0 += 64) {
        __syncthreads();
        for (int idx = t; idx < 32 * 64; idx += 512) {
            int rr = idx >> 6, cc = idx & 63;
            sX[rr][cc] = X[(size_t)(R0 + rr) * INF_ + c0 + cc];
        }
        for (int idx = t; idx < 64 * 64; idx += 512) {
            int cc = idx >> 6, kk = idx & 63;
            sW[cc][kk] = W[(size_t)(c0 + cc) * OUTF + kk];
        }
        __syncthreads();
#pragma unroll 16
        for (int cc = 0; cc < 64; cc++) {
            float x = sX[r][cc];
            float4 w = *reinterpret_cast<const float4*>(&sW[cc][k0]);
            acc.x = fmaf(x, w.x, acc.x);
            acc.y = fmaf(x, w.y, acc.y);
            acc.z = fmaf(x, w.z, acc.z);
            acc.w = fmaf(x, w.w, acc.w);
        }
    }

    int row = R0 + r;
    half2 h0 = __floats2half2_rn(acc.x, acc.y);
    half2 h1 = __floats2half2_rn(acc.z, acc.w);
    uint2 uu;
    uu.x = *reinterpret_cast<unsigned*>(&h0);
    uu.y = *reinterpret_cast<unsigned*>(&h1);
    *reinterpret_cast<uint2*>(&g_hpH[(size_t)row * 72 + k0]) = uu;
    if (q == 0) {
        uint4 ones = make_uint4(0x00003C00u, 0u, 0u, 0u); // half(1.0), then zeros
        *reinterpret_cast<uint4*>(&g_hpH[(size_t)row * 72 + 64]) = ones;
    }

    float4 A1 = *reinterpret_cast<const float4*>(&a1[k0]);
    float4 A2 = *reinterpret_cast<const float4*>(&a2[k0]);
    float s1p = acc.x * A1.x + acc.y * A1.y + acc.z * A1.z + acc.w * A1.w;
    float s2p = acc.x * A2.x + acc.y * A2.y + acc.z * A2.z + acc.w * A2.w;
#pragma unroll
    for (int o = 8; o; o >>= 1) {
        s1p += __shfl_down_sync(0xffffffffu, s1p, o, 16);
        s2p += __shfl_down_sync(0xffffffffu, s2p, o, 16);
    }
    if (q == 0) {
        g_s1[row] = s1p;
        g_B[row] = exp2f(LOG2E * s2p);
        g_D[row] = exp2f(ALPHA * LOG2E * s2p);
        int b = __float_as_int(s2p);
        unsigned u = (unsigned)b ^ ((unsigned)(b >> 31) | 0x80000000u);
        atomicMax(&g_s2max_u, u);
    }
}

// ---------------- mma helpers ----------------
__device__ __forceinline__ void ldsm_x4(unsigned* r, const void* p) {
    unsigned a = (unsigned)__cvta_generic_to_shared(p);
    asm volatile("ldmatrix.sync.aligned.m8n8.x4.shared.b16 {%0,%1,%2,%3},[%4];"
                 : "=r"(r[0]), "=r"(r[1]), "=r"(r[2]), "=r"(r[3]) : "r"(a));
}
__device__ __forceinline__ void ldsm_x4t(unsigned* r, const void* p) {
    unsigned a = (unsigned)__cvta_generic_to_shared(p);
    asm volatile("ldmatrix.sync.aligned.m8n8.x4.trans.shared.b16 {%0,%1,%2,%3},[%4];"
                 : "=r"(r[0]), "=r"(r[1]), "=r"(r[2]), "=r"(r[3]) : "r"(a));
}
__device__ __forceinline__ void ldsm_x2t(unsigned* r, const void* p) {
    unsigned a = (unsigned)__cvta_generic_to_shared(p);
    asm volatile("ldmatrix.sync.aligned.m8n8.x2.trans.shared.b16 {%0,%1},[%2];"
                 : "=r"(r[0]), "=r"(r[1]) : "r"(a));
}
__device__ __forceinline__ void mma_16816(float* c, const unsigned* a, const unsigned* b) {
    asm volatile(
        "mma.sync.aligned.m16n8k16.row.col.f32.f16.f16.f32 "
        "{%0,%1,%2,%3},{%4,%5,%6,%7},{%8,%9},{%0,%1,%2,%3};"
        : "+f"(c[0]), "+f"(c[1]), "+f"(c[2]), "+f"(c[3])
        : "r"(a[0]), "r"(a[1]), "r"(a[2]), "r"(a[3]), "r"(b[0]), "r"(b[1]));
}

// ---------------- fused GAT: 128 blocks x 64 rows, 8 warps ----------------
__global__ __launch_bounds__(256, 1) void gat_kernel(const int* __restrict__ adj,
                                                     float* __restrict__ out) {
    __shared__ __half sP[64 * 136];   // P tile (stride 136 halves: conflict-free ldsm)
    __shared__ __half sB[128 * 72];   // h' chunk incl. ones column
    __shared__ float sA[64], sC[64], sT[64], sL[64];

    int t = threadIdx.x;
    int w = t >> 5, lane = t & 31;
    int I0 = blockIdx.x * 64;

    unsigned su = g_s2max_u;
    float S2max = (su & 0x80000000u) ? __uint_as_float(su ^ 0x80000000u)
                                     : __uint_as_float(~su);
    if (t < 64) {
        float s1 = g_s1[I0 + t];
        float v = s1 + S2max;
        float m = fmaxf(v, ALPHA * v);          // leaky(s1+S2max) >= row max -> weights <= 1
        sA[t] = PSCALE * exp2f(LOG2E * (s1 - m));
        sC[t] = PSCALE * exp2f(LOG2E * (ALPHA * s1 - m));
        sT[t] = exp2f(-LOG2E * s1);             // branch threshold on B_j
    }
    __syncthreads();

    float acc[5][4];
#pragma unroll
    for (int i = 0; i < 5; i++)
#pragma unroll
        for (int j = 0; j < 4; j++) acc[i][j] = 0.f;

    int rg = w & 3, cg = w >> 2;
    int jt = lane * 4;
    int cshift = (lane >> 4) << 3;
    const int4* adj4 = reinterpret_cast<const int4*>(adj);

    // prefetch adj chunk 0 (warp w owns P rows {w, 8+w, ..., 56+w})
    int4 cur[8];
#pragma unroll
    for (int rr = 0; rr < 8; rr++)
        cur[rr] = adj4[(size_t)(I0 + rr * 8 + w) * (NNODES / 4) + lane];

    for (int c = 0; c < 64; c++) {
        int J0 = c * 128;
        // async-load h' chunk [J0..J0+127][0..71] (L2-resident)
        for (int idx = t; idx < 128 * 9; idx += 256) {
            int rrow = idx / 9, seg = idx - rrow * 9;
            unsigned dst = (unsigned)__cvta_generic_to_shared(&sB[rrow * 72 + seg * 8]);
            const __half* src = &g_hpH[(size_t)(J0 + rrow) * 72 + seg * 8];
            asm volatile("cp.async.cg.shared.global [%0], [%1], 16;\n" ::"r"(dst), "l"(src));
        }
        asm volatile("cp.async.commit_group;\n");

        // prefetch next adj chunk (consumed only after this chunk's MMA)
        int4 nxt[8];
        if (c < 63) {
#pragma unroll
            for (int rr = 0; rr < 8; rr++)
                nxt[rr] = adj4[(size_t)(I0 + rr * 8 + w) * (NNODES / 4) + (J0 + 128 + jt) / 4];
        }

        // P generation: zero-MUFU separable softmax numerator, adj-masked
        float4 Bv = *reinterpret_cast<const float4*>(&g_B[J0 + jt]);
        float4 Dv = *reinterpret_cast<const float4*>(&g_D[J0 + jt]);
#pragma unroll
        for (int rr = 0; rr < 8; rr++) {
            int i = rr * 8 + w;
            float Ai = sA[i], Ci = sC[i], Ti = sT[i];
            int4 av = cur[rr];
            float v0 = (Bv.x >= Ti) ? Ai * Bv.x : Ci * Dv.x; if (av.x <= 0) v0 = 0.f;
            float v1 = (Bv.y >= Ti) ? Ai * Bv.y : Ci * Dv.y; if (av.y <= 0) v1 = 0.f;
            float v2 = (Bv.z >= Ti) ? Ai * Bv.z : Ci * Dv.z; if (av.z <= 0) v2 = 0.f;
            float v3 = (Bv.w >= Ti) ? Ai * Bv.w : Ci * Dv.w; if (av.w <= 0) v3 = 0.f;
            half2 h01 = __floats2half2_rn(v0, v1);
            half2 h23 = __floats2half2_rn(v2, v3);
            uint2 uu;
            uu.x = *reinterpret_cast<unsigned*>(&h01);
            uu.y = *reinterpret_cast<unsigned*>(&h23);
            *reinterpret_cast<uint2*>(&sP[i * 136 + jt]) = uu;
        }

        asm volatile("cp.async.wait_group 0;\n");
        __syncthreads();

        // O[64x72] += P[64x128] @ B[128x72]; warp = (row group rg, col half cg)
#pragma unroll
        for (int ks = 0; ks < 8; ks++) {
            unsigned a[4];
            ldsm_x4(a, &sP[(rg * 16 + (lane & 15)) * 136 + ks * 16 + cshift]);
            int brow = ks * 16 + (lane & 15);
            unsigned b[4];
            if (cg == 0) {
                ldsm_x4t(b, &sB[brow * 72 + 0 + cshift]);
                mma_16816(acc[0], a, b); mma_16816(acc[1], a, b + 2);
                ldsm_x4t(b, &sB[brow * 72 + 16 + cshift]);
                mma_16816(acc[2], a, b); mma_16816(acc[3], a, b + 2);
                ldsm_x2t(b, &sB[brow * 72 + 32]);
                mma_16816(acc[4], a, b);
            } else {
                ldsm_x4t(b, &sB[brow * 72 + 40 + cshift]);
                mma_16816(acc[0], a, b); mma_16816(acc[1], a, b + 2);
                ldsm_x4t(b, &sB[brow * 72 + 56 + cshift]);
                mma_16816(acc[2], a, b); mma_16816(acc[3], a, b + 2);
            }
        }

        // retire prefetched adj into cur (load already landed under MMA)
#pragma unroll
        for (int rr = 0; rr < 8; rr++) cur[rr] = nxt[rr];
        __syncthreads();   // protect sP/sB from next chunk's writers
    }

    // ---- epilogue: l from ones-column (col 64 = cg1 tile 3, in-tile col 0) ----
    if (cg == 1 && (lane & 3) == 0) {
        int g = lane >> 2;
        sL[rg * 16 + g]     = acc[3][0];
        sL[rg * 16 + g + 8] = acc[3][2];
    }
    __syncthreads();

    int g = lane >> 2, tt = lane & 3;
    int r0 = rg * 16 + g, r1 = r0 + 8;
    float inv0 = 1.f / sL[r0];
    float inv1 = 1.f / sL[r1];
    int ntiles = cg ? 3 : 5;          // cg1 skips cols >= 64 (ones/pad)
    int cbase  = cg ? 40 : 0;
#pragma unroll
    for (int ti = 0; ti < 5; ti++) {
        if (ti >= ntiles) break;
        int cb = cbase + ti * 8 + 2 * tt;
        float o00 = acc[ti][0] * inv0, o01 = acc[ti][1] * inv0;
        float o10 = acc[ti][2] * inv1, o11 = acc[ti][3] * inv1;
        o00 = o00 > 0.f ? o00 : expm1f(o00);
        o01 = o01 > 0.f ? o01 : expm1f(o01);
        o10 = o10 > 0.f ? o10 : expm1f(o10);
        o11 = o11 > 0.f ? o11 : expm1f(o11);
        out[(size_t)(I0 + r0) * OUTF + cb]     = o00;
        out[(size_t)(I0 + r0) * OUTF + cb + 1] = o01;
        out[(size_t)(I0 + r1) * OUTF + cb]     = o10;
        out[(size_t)(I0 + r1) * OUTF + cb + 1] = o11;
    }
}

extern "C" void kernel_launch(void* const* d_in, const int* in_sizes, int n_in,
                              void* d_out, int out_size) {
    const float* X   = (const float*)d_in[0];
    const int*   adj = (const int*)d_in[1];
    const float* W   = (const float*)d_in[2];
    const float* a1  = (const float*)d_in[3];
    const float* a2  = (const float*)d_in[4];
    float* out = (float*)d_out;

    reset_kernel<<<1, 1>>>();
    prep_kernel<<<NNODES / 32, 512>>>(X, W, a1, a2);
    gat_kernel<<<NNODES / 64, 256>>>(adj, out);
}

// round 4
// speedup vs baseline: 1.0716x; 1.0716x over previous
#include <cuda_runtime.h>
#include <cuda_fp16.h>
#include <cstdint>
#include <cstddef>

#define NNODES 8192
#define INF_ 256
#define OUTF 64
#define ALPHA 0.2f
#define LOG2E 1.4426950408889634f
#define PSCALE 256.0f   // scales numerator & denominator identically (cancels)

// ---------------- device scratch (no allocations allowed) ----------------
__device__ __align__(16) __half g_hpH[(size_t)NNODES * 72]; // cols 0-63 h', col 64 = 1, 65-71 = 0
__device__ float g_s1[NNODES];
__device__ float g_B[NNODES];        // exp(s2_j)
__device__ float g_D[NNODES];        // exp(ALPHA*s2_j)
__device__ float g_s2part[NNODES / 32]; // per-prep-block max of s2

// ---------------- prep: h' = X@W (fp32), s1, s2, B, D, s2 block-max ----------------
__global__ __launch_bounds__(512) void prep_kernel(const float* __restrict__ X,
                                                   const float* __restrict__ W,
                                                   const float* __restrict__ a1,
                                                   const float* __restrict__ a2) {
    __shared__ float sX[32][64];
    __shared__ float sW[64][64];
    __shared__ float sMax[32];
    int t = threadIdx.x;
    int r = t >> 4;           // 0..31 local row
    int q = t & 15;           // 0..15 -> 4 output cols each
    int k0 = q * 4;
    int R0 = blockIdx.x * 32;

    float4 acc = make_float4(0.f, 0.f, 0.f, 0.f);
    for (int c0 = 0; c0 < INF_; c0 += 64) {
        __syncthreads();
        for (int idx = t; idx < 32 * 64; idx += 512) {
            int rr = idx >> 6, cc = idx & 63;
            sX[rr][cc] = X[(size_t)(R0 + rr) * INF_ + c0 + cc];
        }
        for (int idx = t; idx < 64 * 64; idx += 512) {
            int cc = idx >> 6, kk = idx & 63;
            sW[cc][kk] = W[(size_t)(c0 + cc) * OUTF + kk];
        }
        __syncthreads();
#pragma unroll 16
        for (int cc = 0; cc < 64; cc++) {
            float x = sX[r][cc];
            float4 w = *reinterpret_cast<const float4*>(&sW[cc][k0]);
            acc.x = fmaf(x, w.x, acc.x);
            acc.y = fmaf(x, w.y, acc.y);
            acc.z = fmaf(x, w.z, acc.z);
            acc.w = fmaf(x, w.w, acc.w);
        }
    }

    int row = R0 + r;
    half2 h0 = __floats2half2_rn(acc.x, acc.y);
    half2 h1 = __floats2half2_rn(acc.z, acc.w);
    uint2 uu;
    uu.x = *reinterpret_cast<unsigned*>(&h0);
    uu.y = *reinterpret_cast<unsigned*>(&h1);
    *reinterpret_cast<uint2*>(&g_hpH[(size_t)row * 72 + k0]) = uu;
    if (q == 0) {
        uint4 ones = make_uint4(0x00003C00u, 0u, 0u, 0u); // half(1.0), then zeros
        *reinterpret_cast<uint4*>(&g_hpH[(size_t)row * 72 + 64]) = ones;
    }

    float4 A1 = *reinterpret_cast<const float4*>(&a1[k0]);
    float4 A2 = *reinterpret_cast<const float4*>(&a2[k0]);
    float s1p = acc.x * A1.x + acc.y * A1.y + acc.z * A1.z + acc.w * A1.w;
    float s2p = acc.x * A2.x + acc.y * A2.y + acc.z * A2.z + acc.w * A2.w;
#pragma unroll
    for (int o = 8; o; o >>= 1) {
        s1p += __shfl_down_sync(0xffffffffu, s1p, o, 16);
        s2p += __shfl_down_sync(0xffffffffu, s2p, o, 16);
    }
    if (q == 0) {
        g_s1[row] = s1p;
        g_B[row] = exp2f(LOG2E * s2p);
        g_D[row] = exp2f(ALPHA * LOG2E * s2p);
        sMax[r] = s2p;
    }
    __syncthreads();
    if (t == 0) {
        float m = sMax[0];
#pragma unroll
        for (int i = 1; i < 32; i++) m = fmaxf(m, sMax[i]);
        g_s2part[blockIdx.x] = m;
    }
}

// ---------------- mma helpers ----------------
__device__ __forceinline__ void ldsm_x4(unsigned* r, const void* p) {
    unsigned a = (unsigned)__cvta_generic_to_shared(p);
    asm volatile("ldmatrix.sync.aligned.m8n8.x4.shared.b16 {%0,%1,%2,%3},[%4];"
                 : "=r"(r[0]), "=r"(r[1]), "=r"(r[2]), "=r"(r[3]) : "r"(a));
}
__device__ __forceinline__ void ldsm_x4t(unsigned* r, const void* p) {
    unsigned a = (unsigned)__cvta_generic_to_shared(p);
    asm volatile("ldmatrix.sync.aligned.m8n8.x4.trans.shared.b16 {%0,%1,%2,%3},[%4];"
                 : "=r"(r[0]), "=r"(r[1]), "=r"(r[2]), "=r"(r[3]) : "r"(a));
}
__device__ __forceinline__ void ldsm_x2t(unsigned* r, const void* p) {
    unsigned a = (unsigned)__cvta_generic_to_shared(p);
    asm volatile("ldmatrix.sync.aligned.m8n8.x2.trans.shared.b16 {%0,%1},[%2];"
                 : "=r"(r[0]), "=r"(r[1]) : "r"(a));
}
__device__ __forceinline__ void mma_16816(float* c, const unsigned* a, const unsigned* b) {
    asm volatile(
        "mma.sync.aligned.m16n8k16.row.col.f32.f16.f16.f32 "
        "{%0,%1,%2,%3},{%4,%5,%6,%7},{%8,%9},{%0,%1,%2,%3};"
        : "+f"(c[0]), "+f"(c[1]), "+f"(c[2]), "+f"(c[3])
        : "r"(a[0]), "r"(a[1]), "r"(a[2]), "r"(a[3]), "r"(b[0]), "r"(b[1]));
}

// Dynamic smem layout (bytes):
//   sP   : 64*136 halves            = 17408
//   sB   : 2 * 128*72 halves        = 73728   (double buffer)
//   sA/sC/sT/sL : 4 * 64 floats     = 1024
#define SMEM_P_OFF 0
#define SMEM_B_OFF 17408
#define SMEM_F_OFF (17408 + 73728)
#define SMEM_TOTAL (SMEM_F_OFF + 1024)

// ---------------- fused GAT: 128 blocks x 64 rows, 16 warps ----------------
__global__ __launch_bounds__(512, 1) void gat_kernel(const int* __restrict__ adj,
                                                     float* __restrict__ out) {
    extern __shared__ char smem[];
    __half* sP = reinterpret_cast<__half*>(smem + SMEM_P_OFF);
    __half* sBb = reinterpret_cast<__half*>(smem + SMEM_B_OFF);
    float* sA = reinterpret_cast<float*>(smem + SMEM_F_OFF);
    float* sC = sA + 64;
    float* sT = sA + 128;
    float* sL = sA + 192;
    float* sRed = reinterpret_cast<float*>(smem); // aliases sP, prologue only

    int t = threadIdx.x;
    int w = t >> 5, lane = t & 31;
    int I0 = blockIdx.x * 64;

    // ---- reduce global s2 max from prep partials ----
    if (t < 256) sRed[t] = g_s2part[t];
    __syncthreads();
    if (t < 32) {
        float m = sRed[t];
#pragma unroll
        for (int k = 1; k < 8; k++) m = fmaxf(m, sRed[t + 32 * k]);
#pragma unroll
        for (int o = 16; o; o >>= 1) m = fmaxf(m, __shfl_xor_sync(0xffffffffu, m, o));
        if (t == 0) sRed[0] = m;
    }
    __syncthreads();
    float S2max = sRed[0];
    __syncthreads();   // done aliasing sP

    if (t < 64) {
        float s1 = g_s1[I0 + t];
        float v = s1 + S2max;
        float m = fmaxf(v, ALPHA * v);          // leaky(s1+S2max) >= row max -> weights <= 1
        sA[t] = PSCALE * exp2f(LOG2E * (s1 - m));
        sC[t] = PSCALE * exp2f(LOG2E * (ALPHA * s1 - m));
        sT[t] = exp2f(-LOG2E * s1);             // branch threshold on B_j
    }

    float acc[3][4];
#pragma unroll
    for (int i = 0; i < 3; i++)
#pragma unroll
        for (int j = 0; j < 4; j++) acc[i][j] = 0.f;

    int rg = w & 3, cg = w >> 2;   // 4 row-groups x 4 col-groups
    int jt = lane * 4;
    int cshift = (lane >> 4) << 3;
    const int4* adj4 = reinterpret_cast<const int4*>(adj);

    // prefetch adj chunk 0: warp w owns P rows {w, 16+w, 32+w, 48+w}
    int4 cur[4];
#pragma unroll
    for (int rr = 0; rr < 4; rr++)
        cur[rr] = adj4[(size_t)(I0 + rr * 16 + w) * (NNODES / 4) + lane];

    // prologue: load sB chunk 0 into buffer 0
    for (int idx = t; idx < 128 * 9; idx += 512) {
        int rrow = idx / 9, seg = idx - rrow * 9;
        unsigned dst = (unsigned)__cvta_generic_to_shared(&sBb[rrow * 72 + seg * 8]);
        const __half* src = &g_hpH[(size_t)rrow * 72 + seg * 8];
        asm volatile("cp.async.cg.shared.global [%0], [%1], 16;\n" ::"r"(dst), "l"(src));
    }
    asm volatile("cp.async.commit_group;\n");
    __syncthreads();   // sA/sC/sT visible

    for (int c = 0; c < 64; c++) {
        int J0 = c * 128;
        __half* sBc = sBb + (c & 1) * (128 * 72);

        // issue next sB chunk into other buffer (group c+1)
        if (c < 63) {
            __half* sBn = sBb + ((c + 1) & 1) * (128 * 72);
            for (int idx = t; idx < 128 * 9; idx += 512) {
                int rrow = idx / 9, seg = idx - rrow * 9;
                unsigned dst = (unsigned)__cvta_generic_to_shared(&sBn[rrow * 72 + seg * 8]);
                const __half* src = &g_hpH[(size_t)(J0 + 128 + rrow) * 72 + seg * 8];
                asm volatile("cp.async.cg.shared.global [%0], [%1], 16;\n" ::"r"(dst), "l"(src));
            }
        }
        asm volatile("cp.async.commit_group;\n");

        // prefetch next adj chunk into registers (lands under P-gen + MMA)
        int4 nxt[4];
        if (c < 63) {
#pragma unroll
            for (int rr = 0; rr < 4; rr++)
                nxt[rr] = adj4[(size_t)(I0 + rr * 16 + w) * (NNODES / 4) + (J0 + 128) / 4 + lane];
        }

        // P generation: zero-MUFU separable softmax numerator, adj-masked
        float4 Bv = *reinterpret_cast<const float4*>(&g_B[J0 + jt]);
        float4 Dv = *reinterpret_cast<const float4*>(&g_D[J0 + jt]);
#pragma unroll
        for (int rr = 0; rr < 4; rr++) {
            int i = rr * 16 + w;
            float Ai = sA[i], Ci = sC[i], Ti = sT[i];
            int4 av = cur[rr];
            float v0 = (Bv.x >= Ti) ? Ai * Bv.x : Ci * Dv.x; if (av.x <= 0) v0 = 0.f;
            float v1 = (Bv.y >= Ti) ? Ai * Bv.y : Ci * Dv.y; if (av.y <= 0) v1 = 0.f;
            float v2 = (Bv.z >= Ti) ? Ai * Bv.z : Ci * Dv.z; if (av.z <= 0) v2 = 0.f;
            float v3 = (Bv.w >= Ti) ? Ai * Bv.w : Ci * Dv.w; if (av.w <= 0) v3 = 0.f;
            half2 h01 = __floats2half2_rn(v0, v1);
            half2 h23 = __floats2half2_rn(v2, v3);
            uint2 uu;
            uu.x = *reinterpret_cast<unsigned*>(&h01);
            uu.y = *reinterpret_cast<unsigned*>(&h23);
            *reinterpret_cast<uint2*>(&sP[i * 136 + jt]) = uu;
        }

        asm volatile("cp.async.wait_group 1;\n");  // chunk c landed; c+1 in flight
        __syncthreads();

        // O[64x72] += P[64x128] @ B[128x72]
        // warp (rg,cg): rows rg*16..+15, cols cg*16..+15 (cg3 also cols 64-71 = denominator)
#pragma unroll
        for (int ks = 0; ks < 8; ks++) {
            unsigned a[4];
            ldsm_x4(a, &sP[(rg * 16 + (lane & 15)) * 136 + ks * 16 + cshift]);
            int brow = ks * 16 + (lane & 15);
            unsigned b[4];
            ldsm_x4t(b, &sBc[brow * 72 + cg * 16 + cshift]);
            mma_16816(acc[0], a, b);
            mma_16816(acc[1], a, b + 2);
            if (cg == 3) {
                unsigned b2[2];
                ldsm_x2t(b2, &sBc[brow * 72 + 64]);
                mma_16816(acc[2], a, b2);
            }
        }

#pragma unroll
        for (int rr = 0; rr < 4; rr++) cur[rr] = nxt[rr];
        __syncthreads();   // protect sP / sB buffers for next chunk writers
    }

    // ---- epilogue: denominator l = ones column (col 64 = cg3 acc[2], in-tile col 0) ----
    if (cg == 3 && (lane & 3) == 0) {
        int g = lane >> 2;
        sL[rg * 16 + g]     = acc[2][0];
        sL[rg * 16 + g + 8] = acc[2][2];
    }
    __syncthreads();

    int g = lane >> 2, tt = lane & 3;
    int r0 = rg * 16 + g, r1 = r0 + 8;
    float inv0 = 1.f / sL[r0];
    float inv1 = 1.f / sL[r1];
#pragma unroll
    for (int ti = 0; ti < 2; ti++) {
        int cb = cg * 16 + ti * 8 + 2 * tt;
        float o00 = acc[ti][0] * inv0, o01 = acc[ti][1] * inv0;
        float o10 = acc[ti][2] * inv1, o11 = acc[ti][3] * inv1;
        o00 = o00 > 0.f ? o00 : expm1f(o00);
        o01 = o01 > 0.f ? o01 : expm1f(o01);
        o10 = o10 > 0.f ? o10 : expm1f(o10);
        o11 = o11 > 0.f ? o11 : expm1f(o11);
        out[(size_t)(I0 + r0) * OUTF + cb]     = o00;
        out[(size_t)(I0 + r0) * OUTF + cb + 1] = o01;
        out[(size_t)(I0 + r1) * OUTF + cb]     = o10;
        out[(size_t)(I0 + r1) * OUTF + cb + 1] = o11;
    }
}

extern "C" void kernel_launch(void* const* d_in, const int* in_sizes, int n_in,
                              void* d_out, int out_size) {
    const float* X   = (const float*)d_in[0];
    const int*   adj = (const int*)d_in[1];
    const float* W   = (const float*)d_in[2];
    const float* a1  = (const float*)d_in[3];
    const float* a2  = (const float*)d_in[4];
    float* out = (float*)d_out;

    static int smem_set = 0;
    if (!smem_set) {
        cudaFuncSetAttribute(gat_kernel, cudaFuncAttributeMaxDynamicSharedMemorySize,
                             SMEM_TOTAL);
        smem_set = 1;
    }

    prep_kernel<<<NNODES / 32, 512>>>(X, W, a1, a2);
    gat_kernel<<<NNODES / 64, 512, SMEM_TOTAL>>>(adj, out);
}